// round 4
// baseline (speedup 1.0000x reference)
#include <cuda_runtime.h>
#include <cstdint>

#define FEAT_DIM     1024
#define MAX_BATCH    65536
#define MAX_CLASSES  128
#define CAP          1024        // per-class capacity: mean 683, sigma 26 -> 13-sigma margin
#define TILES        6
#define KB_THREADS   512
#define KB_WARPS     (KB_THREADS / 32)

// Static scratch (allocation-free per harness rules)
__device__ int          g_label_is_i64;
__device__ int          g_cnt[MAX_CLASSES];
__device__ int          g_index[MAX_CLASSES * CAP];
__device__ float        g_row_dist[MAX_BATCH];
__device__ unsigned int g_done;   // self-resetting last-block counter

// ---------------------------------------------------------------------------
// K0: zero class counters + lane-parallel label-dtype probe.
// int64 little-endian labels in [0,96) => all odd 32-bit words are 0.
// Checking 64 odd words: false-positive prob for int32 labels ~ (1/96)^64 ~ 0.
// ---------------------------------------------------------------------------
__global__ void k0_init_probe(const unsigned int* __restrict__ lw, int num_classes) {
    int t = threadIdx.x;
    if (t < num_classes) g_cnt[t] = 0;
    if (t < 32) {
        unsigned int v = lw[2 * t + 1] | lw[2 * (t + 32) + 1];
        unsigned int any = __ballot_sync(0xffffffffu, v != 0u);
        if (t == 0) g_label_is_i64 = (any == 0u) ? 1 : 0;
    }
}

// ---------------------------------------------------------------------------
// KA: scatter row ids into per-class index lists. List order is
// nondeterministic (atomic cursors) but per-row results downstream are keyed
// by row id, so the final output is bitwise deterministic.
// ---------------------------------------------------------------------------
__global__ void ka_scatter(const unsigned int* __restrict__ lw, int batch) {
    const int i64 = g_label_is_i64;
    for (int r = blockIdx.x * blockDim.x + threadIdx.x; r < batch;
         r += gridDim.x * blockDim.x) {
        int c = i64 ? (int)lw[2 * r] : (int)lw[r];
        int pos = atomicAdd(&g_cnt[c], 1);
        if (pos < CAP) g_index[c * CAP + pos] = r;
    }
}

// ---------------------------------------------------------------------------
// KB: one class per block. Center row lives in smem (loaded once, 4 KB);
// features stream from DRAM. One warp per feature row, ~7 rows/warp.
// Fused deterministic final reduce via last-block pattern.
// ---------------------------------------------------------------------------
__global__ void __launch_bounds__(KB_THREADS)
kb_main(const float* __restrict__ feat,
        const float* __restrict__ centers,
        float* __restrict__ out,
        int batch, int num_classes, int total_blocks) {
    const int c    = blockIdx.x;
    const int tile = blockIdx.y;
    const int warp = threadIdx.x >> 5;
    const int lane = threadIdx.x & 31;

    __shared__ float4 s_center[FEAT_DIM / 4];
    const float4* crow = (const float4*)(centers + (size_t)c * FEAT_DIM);
    for (int i = threadIdx.x; i < FEAT_DIM / 4; i += KB_THREADS)
        s_center[i] = crow[i];
    __syncthreads();

    int cnt = g_cnt[c];
    if (cnt > CAP) cnt = CAP;
    const int gw     = tile * KB_WARPS + warp;
    const int stride = TILES * KB_WARPS;

    for (int i = gw; i < cnt; i += stride) {
        int r = g_index[c * CAP + i];
        const float4* fr = (const float4*)(feat + (size_t)r * FEAT_DIM);
        float acc = 0.0f;
        #pragma unroll
        for (int j = 0; j < FEAT_DIM / 128; j++) {   // 8 x LDG.128 + 8 x LDS.128
            float4 a = fr[lane + 32 * j];
            float4 b = s_center[lane + 32 * j];
            float dx = a.x - b.x, dy = a.y - b.y;
            float dz = a.z - b.z, dw = a.w - b.w;
            acc = fmaf(dx, dx, acc);
            acc = fmaf(dy, dy, acc);
            acc = fmaf(dz, dz, acc);
            acc = fmaf(dw, dw, acc);
        }
        #pragma unroll
        for (int o = 16; o > 0; o >>= 1)
            acc += __shfl_xor_sync(0xffffffffu, acc, o);
        if (lane == 0)
            g_row_dist[r] = fminf(fmaxf(acc, 1e-12f), 1e12f);
    }

    // ---- fused final reduce (last block to finish does it) ----
    __syncthreads();
    __shared__ unsigned int s_last;
    if (threadIdx.x == 0) {
        __threadfence();
        unsigned int v = atomicAdd(&g_done, 1u);
        s_last = (v == (unsigned int)(total_blocks - 1)) ? 1u : 0u;
    }
    __syncthreads();
    if (s_last) {
        // Deterministic: fixed strided assignment, fixed-order double adds.
        double acc = 0.0;
        const float4* rd = (const float4*)g_row_dist;
        const int n4 = batch / 4;
        for (int i = threadIdx.x; i < n4; i += KB_THREADS) {
            float4 v = rd[i];
            acc += (double)v.x + (double)v.y + (double)v.z + (double)v.w;
        }
        __shared__ double sd[KB_THREADS];
        sd[threadIdx.x] = acc;
        __syncthreads();
        for (int s = KB_THREADS / 2; s > 0; s >>= 1) {
            if (threadIdx.x < s) sd[threadIdx.x] += sd[threadIdx.x + s];
            __syncthreads();
        }
        if (threadIdx.x == 0) {
            g_done = 0;  // reset for next graph replay
            out[0] = (float)(sd[0] / (double)batch
                             + (double)(num_classes - 1) * 1e-12);
        }
    }
}

// ---------------------------------------------------------------------------
extern "C" void kernel_launch(void* const* d_in, const int* in_sizes, int n_in,
                              void* d_out, int out_size) {
    const float*        feat    = (const float*)d_in[0];
    const float*        centers = (const float*)d_in[1];
    const unsigned int* labels  = (const unsigned int*)d_in[2];

    const int batch       = in_sizes[0] / FEAT_DIM;   // 65536
    const int num_classes = in_sizes[1] / FEAT_DIM;   // 96
    const int total_blocks = num_classes * TILES;

    k0_init_probe<<<1, 128>>>(labels, num_classes);
    ka_scatter<<<64, 256>>>(labels, batch);
    dim3 gridB(num_classes, TILES);
    kb_main<<<gridB, KB_THREADS>>>(feat, centers, (float*)d_out,
                                   batch, num_classes, total_blocks);
}

// round 6
// speedup vs baseline: 1.8534x; 1.8534x over previous
#include <cuda_runtime.h>
#include <cstdint>

#define FEAT_DIM     1024
#define ROWS_PER_BLK 8
#define BLK_THREADS  256
#define MAX_BLOCKS   (65536 / ROWS_PER_BLK)   // 8192

// Static scratch (allocation-free per harness rules)
__device__ float        g_partials[MAX_BLOCKS];
__device__ unsigned int g_done;   // self-resetting last-block counter

// ---------------------------------------------------------------------------
// Fully fused center loss: per-warp label-dtype probe + per-row squared
// distance + clamp + per-block partial + last-block deterministic reduce.
// One kernel launch total.
// ---------------------------------------------------------------------------
__global__ void __launch_bounds__(BLK_THREADS, 8)
center_loss_fused(const float* __restrict__ feat,
                  const float* __restrict__ centers,
                  const unsigned int* __restrict__ label_words,
                  float* __restrict__ out,
                  int batch, int num_classes, int nblocks) {
    const int warp = threadIdx.x >> 5;
    const int lane = threadIdx.x & 31;
    const int row  = blockIdx.x * ROWS_PER_BLK + warp;

    // ---- per-warp dtype probe (2 cache lines, L1/L2-hot after first warp) ----
    // int64 little-endian labels in [0,96) => all odd 32-bit words are 0.
    // int32 labels with 32 consecutive zero odd-words: prob ~ (1/96)^32 ~ 0.
    unsigned int oddw = label_words[2 * lane + 1];
    unsigned int any  = __ballot_sync(0xffffffffu, oddw != 0u);
    const int is64 = (any == 0u);

    int label = 0;
    if (lane == 0)
        label = is64 ? (int)label_words[2 * row] : (int)label_words[row];
    label = __shfl_sync(0xffffffffu, label, 0);

    // ---- squared L2 distance: 8 x LDG.128 (features, DRAM-stream) +
    //      8 x LDG.128 (center row, L1/L2-resident) per lane ----
    const float4* fr = (const float4*)(feat    + (size_t)row   * FEAT_DIM);
    const float4* cr = (const float4*)(centers + (size_t)label * FEAT_DIM);

    float acc = 0.0f;
    #pragma unroll
    for (int i = 0; i < FEAT_DIM / (4 * 32); i++) {   // 8 iterations
        float4 a = fr[lane + 32 * i];
        float4 b = cr[lane + 32 * i];
        float dx = a.x - b.x, dy = a.y - b.y;
        float dz = a.z - b.z, dw = a.w - b.w;
        acc = fmaf(dx, dx, acc);
        acc = fmaf(dy, dy, acc);
        acc = fmaf(dz, dz, acc);
        acc = fmaf(dw, dw, acc);
    }

    #pragma unroll
    for (int o = 16; o > 0; o >>= 1)
        acc += __shfl_xor_sync(0xffffffffu, acc, o);

    __shared__ float s[ROWS_PER_BLK];
    if (lane == 0)
        s[warp] = fminf(fmaxf(acc, 1e-12f), 1e12f);   // clip(d, 1e-12, 1e12)
    __syncthreads();

    // ---- per-block partial (fixed order -> deterministic) ----
    __shared__ unsigned int s_last;
    if (threadIdx.x == 0) {
        float t = 0.0f;
        #pragma unroll
        for (int i = 0; i < ROWS_PER_BLK; i++) t += s[i];
        g_partials[blockIdx.x] = t;
        __threadfence();
        unsigned int v = atomicAdd(&g_done, 1u);
        s_last = (v == (unsigned int)(nblocks - 1)) ? 1u : 0u;
    }
    __syncthreads();

    // ---- last block: deterministic double-precision final reduce ----
    if (s_last) {
        __threadfence();   // acquire: observe all g_partials writes
        double dacc = 0.0;
        for (int i = threadIdx.x; i < nblocks; i += BLK_THREADS)
            dacc += (double)g_partials[i];

        __shared__ double sd[BLK_THREADS];
        sd[threadIdx.x] = dacc;
        __syncthreads();
        #pragma unroll
        for (int st = BLK_THREADS / 2; st > 0; st >>= 1) {
            if (threadIdx.x < st) sd[threadIdx.x] += sd[threadIdx.x + st];
            __syncthreads();
        }
        if (threadIdx.x == 0) {
            g_done = 0;   // reset for next graph replay (deterministic state)
            out[0] = (float)(sd[0] / (double)batch
                             + (double)(num_classes - 1) * 1e-12);
        }
    }
}

// ---------------------------------------------------------------------------
extern "C" void kernel_launch(void* const* d_in, const int* in_sizes, int n_in,
                              void* d_out, int out_size) {
    const float*        feat    = (const float*)d_in[0];
    const float*        centers = (const float*)d_in[1];
    const unsigned int* labels  = (const unsigned int*)d_in[2];

    const int batch       = in_sizes[0] / FEAT_DIM;   // 65536
    const int num_classes = in_sizes[1] / FEAT_DIM;   // 96
    const int nblocks     = batch / ROWS_PER_BLK;     // 8192

    center_loss_fused<<<nblocks, BLK_THREADS>>>(feat, centers, labels,
                                                (float*)d_out,
                                                batch, num_classes, nblocks);
}